// round 16
// baseline (speedup 1.0000x reference)
#include <cuda_runtime.h>
#include <cuda_fp16.h>
#include <math.h>
#include <stdint.h>

#define BATCH 16
#define NB    1024
#define NS    4096
#define CDIM  768
#define HEADS 12
#define DH    64
#define TOPK  128
#define C4    3072

// ---------------- device scratch ----------------
__device__ float g_tmp[BATCH * (size_t)NB * CDIM];
__device__ float g_ctx[BATCH * (size_t)NB * CDIM];
__device__ float g_x1 [BATCH * (size_t)NB * CDIM];
__device__ unsigned long long g_part[BATCH * 1024];
__device__ __half g_q_h [BATCH * (size_t)NB * CDIM];
__device__ __half g_k_h [BATCH * (size_t)TOPK * CDIM];
__device__ __half g_v_h [BATCH * (size_t)TOPK * CDIM];
__device__ __half g_act_h [BATCH * (size_t)NB * CDIM];
__device__ __half g_sel_h [BATCH * (size_t)TOPK * CDIM];
__device__ __half g_h_h   [BATCH * (size_t)NB * C4];
__device__ __half g_WqT[CDIM * CDIM];
__device__ __half g_WkT[CDIM * CDIM];
__device__ __half g_WvT[CDIM * CDIM];
__device__ __half g_WoT[CDIM * CDIM];
__device__ __half g_Wm1T[(size_t)C4 * CDIM];
__device__ __half g_Wm2T[(size_t)CDIM * C4];
__device__ __half g_s_hi[BATCH * (size_t)NS * CDIM];
__device__ __half g_s_lo[BATCH * (size_t)NS * CDIM];
__device__ __half g_b_hi[BATCH * (size_t)NB * CDIM];
__device__ __half g_b_lo[BATCH * (size_t)NB * CDIM];

// ================= helpers =================
__device__ __forceinline__ uint32_t smem_u32(const void* p) {
    uint32_t a;
    asm("{ .reg .u64 t; cvta.to.shared.u64 t, %1; cvt.u32.u64 %0, t; }" : "=r"(a) : "l"(p));
    return a;
}
__device__ __forceinline__ void cp16(uint32_t dst, const void* src) {
    asm volatile("cp.async.cg.shared.global [%0], [%1], 16;" :: "r"(dst), "l"(src));
}
#define CP_COMMIT() asm volatile("cp.async.commit_group;" ::: "memory")
#define CP_WAIT(n)  asm volatile("cp.async.wait_group %0;" :: "n"(n) : "memory")

#define KCH 32
#define ROWB 80

__device__ __forceinline__ void ldmA(uint32_t addr, uint32_t* f) {
    asm volatile("ldmatrix.sync.aligned.m8n8.x4.shared.b16 {%0,%1,%2,%3}, [%4];"
        : "=r"(f[0]), "=r"(f[1]), "=r"(f[2]), "=r"(f[3]) : "r"(addr));
}
__device__ __forceinline__ void ldmB4(uint32_t addr, uint32_t* f) {
    asm volatile("ldmatrix.sync.aligned.m8n8.x4.shared.b16 {%0,%1,%2,%3}, [%4];"
        : "=r"(f[0]), "=r"(f[1]), "=r"(f[2]), "=r"(f[3]) : "r"(addr));
}
__device__ __forceinline__ void ldmB4T(uint32_t addr, uint32_t* f) {
    asm volatile("ldmatrix.sync.aligned.m8n8.x4.trans.shared.b16 {%0,%1,%2,%3}, [%4];"
        : "=r"(f[0]), "=r"(f[1]), "=r"(f[2]), "=r"(f[3]) : "r"(addr));
}
__device__ __forceinline__ void hmma(float* d, const uint32_t* a, const uint32_t* b) {
    asm volatile(
        "mma.sync.aligned.m16n8k16.row.col.f32.f16.f16.f32 "
        "{%0,%1,%2,%3}, {%4,%5,%6,%7}, {%8,%9}, {%0,%1,%2,%3};"
        : "+f"(d[0]), "+f"(d[1]), "+f"(d[2]), "+f"(d[3])
        : "r"(a[0]), "r"(a[1]), "r"(a[2]), "r"(a[3]), "r"(b[0]), "r"(b[1]));
}
__device__ __forceinline__ uint32_t fenc(float f) {
    uint32_t u = __float_as_uint(f);
    return (u & 0x80000000u) ? ~u : (u | 0x80000000u);
}
__device__ __forceinline__ float fdec(uint32_t u) {
    uint32_t b = (u & 0x80000000u) ? (u & 0x7FFFFFFFu) : ~u;
    return __uint_as_float(b);
}

// ================= GEMM core =================
#define G_ST_B  20480
#define G_SMEM  (4 * G_ST_B)

template <int ACT, int OUTH>
__device__ __forceinline__ void gemm_body(
    char* dsm, const __half* __restrict__ A, const __half* __restrict__ Bt,
    const float* __restrict__ bias, float* __restrict__ Cf,
    __half* __restrict__ Ch, int m0, int n0, int N, int K)
{
    uint32_t su = smem_u32(dsm);
    int tid = threadIdx.x, warp = tid >> 5, lane = tid & 31;
    int wm = (warp >> 1) * 32, wn = (warp & 1) * 64;

    const __half* Ab = A  + (size_t)m0 * K;
    const __half* Bb = Bt + (size_t)n0 * K;

    int row0 = tid >> 2, seg0 = (tid & 3);
    int row1 = (tid + 256) >> 2, seg1 = ((tid + 256) & 3);

    int nch = K / KCH;
#pragma unroll
    for (int s = 0; s < 3; s++) {
        uint32_t sb = su + s * G_ST_B;
        const __half* As = Ab + (size_t)s * KCH;
        const __half* Bs = Bb + (size_t)s * KCH;
        cp16(sb + row0 * ROWB + seg0 * 16, As + (size_t)row0 * K + seg0 * 8);
        cp16(sb + row1 * ROWB + seg1 * 16, As + (size_t)row1 * K + seg1 * 8);
        cp16(sb + 10240 + row0 * ROWB + seg0 * 16, Bs + (size_t)row0 * K + seg0 * 8);
        cp16(sb + 10240 + row1 * ROWB + seg1 * 16, Bs + (size_t)row1 * K + seg1 * 8);
        CP_COMMIT();
    }

    float acc[2][8][4];
#pragma unroll
    for (int i = 0; i < 2; i++)
#pragma unroll
        for (int j = 0; j < 8; j++)
#pragma unroll
            for (int t = 0; t < 4; t++) acc[i][j][t] = 0.f;

    int a_row = lane & 15, a_kh = (lane >> 4) * 8;
    int bp_row = ((lane >> 4) & 1) * 8 + (lane & 7);
    int bp_kh  = ((lane >> 3) & 1) * 8;

    for (int c = 0; c < nch; c++) {
        CP_WAIT(2);
        __syncthreads();
        if (c + 3 < nch) {
            uint32_t sb = su + ((c + 3) & 3) * G_ST_B;
            const __half* As = Ab + (size_t)(c + 3) * KCH;
            const __half* Bs = Bb + (size_t)(c + 3) * KCH;
            cp16(sb + row0 * ROWB + seg0 * 16, As + (size_t)row0 * K + seg0 * 8);
            cp16(sb + row1 * ROWB + seg1 * 16, As + (size_t)row1 * K + seg1 * 8);
            cp16(sb + 10240 + row0 * ROWB + seg0 * 16, Bs + (size_t)row0 * K + seg0 * 8);
            cp16(sb + 10240 + row1 * ROWB + seg1 * 16, Bs + (size_t)row1 * K + seg1 * 8);
        }
        CP_COMMIT();
        uint32_t sb = su + (c & 3) * G_ST_B;
#pragma unroll
        for (int ks = 0; ks < 2; ks++) {
            int kk = ks * 16;
            uint32_t afr[2][4];
#pragma unroll
            for (int mt = 0; mt < 2; mt++)
                ldmA(sb + (wm + mt * 16 + a_row) * ROWB + (kk + a_kh) * 2, afr[mt]);
#pragma unroll
            for (int p = 0; p < 4; p++) {
                uint32_t bfr[4];
                ldmB4(sb + 10240 + (wn + p * 16 + bp_row) * ROWB + (kk + bp_kh) * 2, bfr);
                hmma(acc[0][2 * p],     afr[0], bfr);
                hmma(acc[1][2 * p],     afr[1], bfr);
                hmma(acc[0][2 * p + 1], afr[0], bfr + 2);
                hmma(acc[1][2 * p + 1], afr[1], bfr + 2);
            }
        }
    }

    int g = lane >> 2, t4 = (lane & 3) * 2;
#pragma unroll
    for (int mt = 0; mt < 2; mt++) {
#pragma unroll
        for (int nt = 0; nt < 8; nt++) {
            int col = n0 + wn + nt * 8 + t4;
            float b0 = bias[col], b1 = bias[col + 1];
#pragma unroll
            for (int hf = 0; hf < 2; hf++) {
                int row = m0 + wm + mt * 16 + g + hf * 8;
                float x0 = acc[mt][nt][hf * 2 + 0] + b0;
                float x1 = acc[mt][nt][hf * 2 + 1] + b1;
                if (ACT == 1) {
                    x0 = 0.5f * x0 * (1.0f + erff(x0 * 0.70710678118654752f));
                    x1 = 0.5f * x1 * (1.0f + erff(x1 * 0.70710678118654752f));
                }
                if (OUTH) {
                    *(__half2*)(Ch + (size_t)row * N + col) = __floats2half2_rn(x0, x1);
                } else {
                    *(float2*)(Cf + (size_t)row * N + col) = make_float2(x0, x1);
                }
            }
        }
    }
}

template <int ACT, int OUTH>
__global__ __launch_bounds__(256, 2)
void gemm_mma(const __half* __restrict__ A, const __half* __restrict__ Bt,
              const float* __restrict__ bias, float* __restrict__ Cf,
              __half* __restrict__ Ch, int M, int N, int K)
{
    extern __shared__ char dsm[];
    gemm_body<ACT, OUTH>(dsm, A, Bt, bias, Cf, Ch,
                         blockIdx.y * 128, blockIdx.x * 128, N, K);
}

__global__ __launch_bounds__(256, 2)
void gemm_qkv(const __half* __restrict__ Aq, const __half* __restrict__ Akv,
              const __half* __restrict__ WqT, const __half* __restrict__ WkT,
              const __half* __restrict__ WvT,
              const float* __restrict__ bq, const float* __restrict__ bk,
              const float* __restrict__ bv,
              __half* __restrict__ Cq, __half* __restrict__ Ck, __half* __restrict__ Cv)
{
    extern __shared__ char dsm[];
    int by = blockIdx.y;
    const __half *A, *W;
    const float* bias;
    __half* C;
    int m0;
    if (by < 128)      { A = Aq;  W = WqT; bias = bq; C = Cq; m0 = by * 128; }
    else if (by < 144) { A = Akv; W = WkT; bias = bk; C = Ck; m0 = (by - 128) * 128; }
    else               { A = Akv; W = WvT; bias = bv; C = Cv; m0 = (by - 144) * 128; }
    gemm_body<0, 1>(dsm, A, W, bias, nullptr, C, m0, blockIdx.x * 128, CDIM, CDIM);
}

// ================= saliency: hi-only HMMA + exact rescue, KCH=64, 2-stage =================
#define S2_ST_B   40960                 // A (2x10240) + B (2x10240)
#define S2_BUF    (2 * S2_ST_B)         // 81920
#define S2_ROWMAX S2_BUF
#define S2_EXACT  (S2_BUF + 512)
#define S2_CNT    (S2_BUF + 1024)
#define S2_LIST   (S2_BUF + 1040)
#define S2_CAP    3072
#define S2_SMEM   (S2_LIST + S2_CAP * 8)   // 107,536
#define S_MARGIN  1.0f

__global__ __launch_bounds__(512)
void saliency_mma(const __half* __restrict__ shi, const __half* __restrict__ slo,
                  const __half* __restrict__ bhi, const __half* __restrict__ blo,
                  float* __restrict__ scores)
{
    extern __shared__ char dsm[];
    uint32_t su = smem_u32(dsm);
    uint32_t* rowmax = (uint32_t*)(dsm + S2_ROWMAX);
    uint32_t* exacts = (uint32_t*)(dsm + S2_EXACT);
    uint32_t* cnt    = (uint32_t*)(dsm + S2_CNT);
    uint2*    list   = (uint2*)(dsm + S2_LIST);

    int tid = threadIdx.x, warp = tid >> 5, lane = tid & 31;
    int b = blockIdx.y;
    int r0 = blockIdx.x * 128;
    int wm = (warp >> 1) * 16, wn = (warp & 1) * 64;

    if (tid < 128) { rowmax[tid] = 0x007FFFFFu; exacts[tid] = 0x007FFFFFu; }
    if (tid == 0) *cnt = 0;

    const __half* Ahi  = shi + ((size_t)b * NS + r0) * CDIM;
    const __half* Bhi0 = bhi + (size_t)b * NB * CDIM;

    int prow = tid >> 2, pseg = tid & 3;

    int a_row = lane & 15, a_kh = (lane >> 4) * 8;
    int bp_row = ((lane >> 4) & 1) * 8 + (lane & 7);
    int bp_kh  = ((lane >> 3) & 1) * 8;
    int g = lane >> 2, t4 = (lane & 3) * 2;

    const int NCH = CDIM / 64;   // 12
    const int NIT = 8 * NCH;     // 96

#define S_PREF(it) do { \
        int _jc = (it) / NCH, _c = (it) % NCH; \
        uint32_t sb = su + ((it) & 1) * S2_ST_B; \
        int ko = _c * 64; \
        const __half* Bh = Bhi0 + (size_t)_jc * 128 * CDIM; \
        cp16(sb + prow * ROWB + pseg * 16,         Ahi + (size_t)prow * CDIM + ko + pseg * 8); \
        cp16(sb + 10240 + prow * ROWB + pseg * 16, Ahi + (size_t)prow * CDIM + ko + 32 + pseg * 8); \
        cp16(sb + 20480 + prow * ROWB + pseg * 16, Bh  + (size_t)prow * CDIM + ko + pseg * 8); \
        cp16(sb + 30720 + prow * ROWB + pseg * 16, Bh  + (size_t)prow * CDIM + ko + 32 + pseg * 8); \
    } while (0)

    S_PREF(0); CP_COMMIT();

    float acc[8][4];

    for (int it = 0; it < NIT; it++) {
        int c = it % NCH, jc = it / NCH;
        if (c == 0) {
#pragma unroll
            for (int j = 0; j < 8; j++)
#pragma unroll
                for (int t = 0; t < 4; t++) acc[j][t] = 0.f;
        }
        CP_WAIT(0);
        __syncthreads();
        if (it + 1 < NIT) { S_PREF(it + 1); }
        CP_COMMIT();
        uint32_t sb = su + (it & 1) * S2_ST_B;
#pragma unroll
        for (int ks = 0; ks < 4; ks++) {
            int chunk = ks >> 1, kk = (ks & 1) * 16;
            uint32_t ah[4];
            ldmA(sb + chunk * 10240 + (wm + a_row) * ROWB + (kk + a_kh) * 2, ah);
#pragma unroll
            for (int p = 0; p < 4; p++) {
                uint32_t bh4[4];
                ldmB4(sb + 20480 + chunk * 10240 + (wn + p * 16 + bp_row) * ROWB + (kk + bp_kh) * 2, bh4);
                hmma(acc[2 * p],     ah, bh4);
                hmma(acc[2 * p + 1], ah, bh4 + 2);
            }
        }
        if (c == NCH - 1) {
#pragma unroll
            for (int hf = 0; hf < 2; hf++) {
                int row = wm + g + hf * 8;
                float m = -3.4e38f;
#pragma unroll
                for (int nt = 0; nt < 8; nt++)
                    m = fmaxf(m, fmaxf(acc[nt][hf * 2], acc[nt][hf * 2 + 1]));
                atomicMax(&rowmax[row], fenc(m));
            }
            __syncthreads();
#pragma unroll
            for (int hf = 0; hf < 2; hf++) {
                int row = wm + g + hf * 8;
                float thr = fdec(rowmax[row]) - S_MARGIN;
#pragma unroll
                for (int nt = 0; nt < 8; nt++)
#pragma unroll
                    for (int e = 0; e < 2; e++) {
                        float s = acc[nt][hf * 2 + e];
                        if (s >= thr) {
                            uint32_t idx = atomicAdd(cnt, 1u);
                            if (idx < S2_CAP) {
                                int jg = jc * 128 + wn + nt * 8 + t4 + e;
                                list[idx] = make_uint2(((uint32_t)row << 16) | (uint32_t)jg,
                                                       __float_as_uint(s));
                            }
                        }
                    }
            }
        }
    }
#undef S_PREF

    __syncthreads();
    int n = *cnt; if (n > S2_CAP) n = S2_CAP;
    for (int i = tid; i < n; i += 512) {
        int row = list[i].x >> 16, jg = list[i].x & 0xFFFFu;
        float s = __uint_as_float(list[i].y);
        if (s >= fdec(rowmax[row]) - S_MARGIN) {
            const __half2* ah2 = (const __half2*)(shi + ((size_t)b * NS + r0 + row) * CDIM);
            const __half2* al2 = (const __half2*)(slo + ((size_t)b * NS + r0 + row) * CDIM);
            const __half2* bh2 = (const __half2*)(bhi + ((size_t)b * NB + jg) * CDIM);
            const __half2* bl2 = (const __half2*)(blo + ((size_t)b * NB + jg) * CDIM);
            float dot = 0.f;
#pragma unroll 4
            for (int k2 = 0; k2 < CDIM / 2; k2++) {
                float2 ah = __half22float2(ah2[k2]);
                float2 al = __half22float2(al2[k2]);
                float2 bh = __half22float2(bh2[k2]);
                float2 bl = __half22float2(bl2[k2]);
                float ax = ah.x + al.x, ay = ah.y + al.y;
                float bx = bh.x + bl.x, by = bh.y + bl.y;
                dot += ax * bx + ay * by;
            }
            atomicMax(&exacts[row], fenc(dot));
        }
    }
    __syncthreads();
    if (tid < 128)
        scores[(size_t)b * NS + r0 + tid] = fdec(exacts[tid]) * 0.03608439182435161f;
}

// ================= tensor-core attention =================
#define AT_SMEM 73728
#define AT_Q   0
#define AT_KV  18432
#define AT_P   36864
#define AT_ST  71680
#define QROWB  144
#define PROWB  272

__global__ __launch_bounds__(256)
void attn_kernel(const __half* __restrict__ qh, const __half* __restrict__ kh,
                 const __half* __restrict__ vh,
                 float* __restrict__ attn_out, __half* __restrict__ ctx_h)
{
    extern __shared__ char dsm[];
    uint32_t su = smem_u32(dsm);
    int tid = threadIdx.x, warp = tid >> 5, lane = tid & 31;
    int qt = blockIdx.x, h = blockIdx.y, b = blockIdx.z;
    int qr0 = qt * 128;

    const __half* Qg = qh + ((size_t)(b * NB + qr0)) * CDIM + h * DH;
    const __half* Kg = kh + ((size_t)b * TOPK) * CDIM + h * DH;
    const __half* Vg = vh + ((size_t)b * TOPK) * CDIM + h * DH;

#pragma unroll
    for (int i = 0; i < 4; i++) {
        int idx = tid + i * 256;
        int r = idx >> 3, c = idx & 7;
        *(uint4*)(dsm + AT_Q  + r * QROWB + c * 16) = *(const uint4*)(Qg + (size_t)r * CDIM + c * 8);
        *(uint4*)(dsm + AT_KV + r * QROWB + c * 16) = *(const uint4*)(Kg + (size_t)r * CDIM + c * 8);
    }
    __syncthreads();

    int wm = (warp >> 1) * 32, wn = (warp & 1) * 64;
    int a_row = lane & 15, a_kh = (lane >> 4) * 8;
    int bp_row = ((lane >> 4) & 1) * 8 + (lane & 7);
    int bp_kh  = ((lane >> 3) & 1) * 8;

    float acc[2][8][4];
#pragma unroll
    for (int i = 0; i < 2; i++)
#pragma unroll
        for (int j = 0; j < 8; j++)
#pragma unroll
            for (int t = 0; t < 4; t++) acc[i][j][t] = 0.f;

#pragma unroll
    for (int ks = 0; ks < 4; ks++) {
        int kk = ks * 16;
        uint32_t afr[2][4];
#pragma unroll
        for (int mt = 0; mt < 2; mt++)
            ldmA(su + AT_Q + (wm + mt * 16 + a_row) * QROWB + (kk + a_kh) * 2, afr[mt]);
#pragma unroll
        for (int p = 0; p < 4; p++) {
            uint32_t bfr[4];
            ldmB4(su + AT_KV + (wn + p * 16 + bp_row) * QROWB + (kk + bp_kh) * 2, bfr);
            hmma(acc[0][2 * p],     afr[0], bfr);
            hmma(acc[1][2 * p],     afr[1], bfr);
            hmma(acc[0][2 * p + 1], afr[0], bfr + 2);
            hmma(acc[1][2 * p + 1], afr[1], bfr + 2);
        }
    }
    __syncthreads();

#pragma unroll
    for (int i = 0; i < 4; i++) {
        int idx = tid + i * 256;
        int r = idx >> 3, c = idx & 7;
        *(uint4*)(dsm + AT_KV + r * QROWB + c * 16) = *(const uint4*)(Vg + (size_t)r * CDIM + c * 8);
    }

    float* rstat = (float*)(dsm + AT_ST);
    int g = lane >> 2, t4 = (lane & 3) * 2;

#pragma unroll
    for (int i = 0; i < 2; i++)
#pragma unroll
        for (int j = 0; j < 8; j++)
#pragma unroll
            for (int t = 0; t < 4; t++) acc[i][j][t] *= 0.125f;

    float gmax[2][2];
#pragma unroll
    for (int mt = 0; mt < 2; mt++)
#pragma unroll
        for (int hf = 0; hf < 2; hf++) {
            float m = -3.4e38f;
#pragma unroll
            for (int nt = 0; nt < 8; nt++)
                m = fmaxf(m, fmaxf(acc[mt][nt][hf * 2], acc[mt][nt][hf * 2 + 1]));
            m = fmaxf(m, __shfl_xor_sync(0xffffffffu, m, 1));
            m = fmaxf(m, __shfl_xor_sync(0xffffffffu, m, 2));
            if ((lane & 3) == 0)
                rstat[(wm + mt * 16 + g + hf * 8) * 2 + (warp & 1)] = m;
        }
    __syncthreads();
#pragma unroll
    for (int mt = 0; mt < 2; mt++)
#pragma unroll
        for (int hf = 0; hf < 2; hf++) {
            int row = wm + mt * 16 + g + hf * 8;
            gmax[mt][hf] = fmaxf(rstat[row * 2], rstat[row * 2 + 1]);
        }
    __syncthreads();

    float gsum[2][2];
#pragma unroll
    for (int mt = 0; mt < 2; mt++)
#pragma unroll
        for (int hf = 0; hf < 2; hf++) {
            float s = 0.f;
#pragma unroll
            for (int nt = 0; nt < 8; nt++) {
                float e0 = expf(acc[mt][nt][hf * 2]     - gmax[mt][hf]);
                float e1 = expf(acc[mt][nt][hf * 2 + 1] - gmax[mt][hf]);
                acc[mt][nt][hf * 2] = e0; acc[mt][nt][hf * 2 + 1] = e1;
                s += e0 + e1;
            }
            s += __shfl_xor_sync(0xffffffffu, s, 1);
            s += __shfl_xor_sync(0xffffffffu, s, 2);
            if ((lane & 3) == 0)
                rstat[(wm + mt * 16 + g + hf * 8) * 2 + (warp & 1)] = s;
        }
    __syncthreads();
#pragma unroll
    for (int mt = 0; mt < 2; mt++)
#pragma unroll
        for (int hf = 0; hf < 2; hf++) {
            int row = wm + mt * 16 + g + hf * 8;
            gsum[mt][hf] = 1.0f / (rstat[row * 2] + rstat[row * 2 + 1]);
        }

#pragma unroll
    for (int mt = 0; mt < 2; mt++)
#pragma unroll
        for (int hf = 0; hf < 2; hf++) {
            int row = wm + mt * 16 + g + hf * 8;
            size_t o = (((size_t)(b * HEADS + h)) * NB + qr0 + row) * TOPK;
            float inv = gsum[mt][hf];
#pragma unroll
            for (int nt = 0; nt < 8; nt++) {
                int col = wn + nt * 8 + t4;
                float p0 = acc[mt][nt][hf * 2]     * inv;
                float p1 = acc[mt][nt][hf * 2 + 1] * inv;
                *(float2*)(attn_out + o + col) = make_float2(p0, p1);
                *(__half2*)(dsm + AT_P + row * PROWB + col * 2) = __floats2half2_rn(p0, p1);
            }
        }
    __syncthreads();

    int wq = warp * 16;
    float acc2[8][4];
#pragma unroll
    for (int j = 0; j < 8; j++)
#pragma unroll
        for (int t = 0; t < 4; t++) acc2[j][t] = 0.f;

    int vt = lane >> 3, vr = lane & 7;
#pragma unroll
    for (int ks = 0; ks < 8; ks++) {
        int kk = ks * 16;
        uint32_t ap[4];
        ldmA(su + AT_P + (wq + a_row) * PROWB + (kk + a_kh) * 2, ap);
#pragma unroll
        for (int p = 0; p < 4; p++) {
            uint32_t bv[4];
            uint32_t addr = su + AT_KV + (kk + (vt & 1) * 8 + vr) * QROWB + (p * 16 + (vt >> 1) * 8) * 2;
            ldmB4T(addr, bv);
            hmma(acc2[2 * p],     ap, bv);
            hmma(acc2[2 * p + 1], ap, bv + 2);
        }
    }
#pragma unroll
    for (int nt = 0; nt < 8; nt++)
#pragma unroll
        for (int hf = 0; hf < 2; hf++) {
            int row = wq + g + hf * 8;
            int col = nt * 8 + t4;
            *(__half2*)(ctx_h + ((size_t)(b * NB + qr0 + row)) * CDIM + h * DH + col) =
                __floats2half2_rn(acc2[nt][hf * 2], acc2[nt][hf * 2 + 1]);
        }
}

// ================= fused converts (8 floats/thread, 16B stores) =================
#define N8S (BATCH * NS * CDIM / 8)
#define N8B (BATCH * NB * CDIM / 8)
struct alignas(16) H8 { __half2 a, b, c, d; };

__global__ __launch_bounds__(256)
void cvt_split_all(const float* __restrict__ sampled, const float* __restrict__ base,
                   __half* __restrict__ shi, __half* __restrict__ slo,
                   __half* __restrict__ bhi, __half* __restrict__ blo)
{
    int i = blockIdx.x * 256 + threadIdx.x;
    const float* in;
    __half *hi, *lo;
    int j;
    if (i < N8S) { in = sampled; hi = shi; lo = slo; j = i; }
    else if (i < N8S + N8B) { in = base; hi = bhi; lo = blo; j = i - N8S; }
    else return;
    const float4* f4 = (const float4*)in + 2 * (size_t)j;
    float4 a = f4[0], bb = f4[1];
    float h0 = __half2float(__float2half_rn(a.x));
    float h1 = __half2float(__float2half_rn(a.y));
    float h2 = __half2float(__float2half_rn(a.z));
    float h3 = __half2float(__float2half_rn(a.w));
    float h4 = __half2float(__float2half_rn(bb.x));
    float h5 = __half2float(__float2half_rn(bb.y));
    float h6 = __half2float(__float2half_rn(bb.z));
    float h7 = __half2float(__float2half_rn(bb.w));
    H8 vh, vl;
    vh.a = __floats2half2_rn(a.x, a.y);   vh.b = __floats2half2_rn(a.z, a.w);
    vh.c = __floats2half2_rn(bb.x, bb.y); vh.d = __floats2half2_rn(bb.z, bb.w);
    vl.a = __floats2half2_rn(a.x - h0, a.y - h1);
    vl.b = __floats2half2_rn(a.z - h2, a.w - h3);
    vl.c = __floats2half2_rn(bb.x - h4, bb.y - h5);
    vl.d = __floats2half2_rn(bb.z - h6, bb.w - h7);
    ((H8*)hi)[j] = vh;
    ((H8*)lo)[j] = vl;
}

// ================= fused weight transposes =================
__global__ __launch_bounds__(256)
void transpose_all(const float* __restrict__ Wq, const float* __restrict__ Wk,
                   const float* __restrict__ Wv, const float* __restrict__ Wo,
                   const float* __restrict__ Wm1, const float* __restrict__ Wm2,
                   __half* __restrict__ WqT, __half* __restrict__ WkT,
                   __half* __restrict__ WvT, __half* __restrict__ WoT,
                   __half* __restrict__ Wm1T, __half* __restrict__ Wm2T)
{
    __shared__ float t[32][33];
    int tb = blockIdx.x;
    const float* in;
    __half* out;
    int K, N, nx, local;
    if (tb < 2304) {
        int w = tb / 576; local = tb % 576; K = CDIM; N = CDIM; nx = 24;
        if (w == 0)      { in = Wq; out = WqT; }
        else if (w == 1) { in = Wk; out = WkT; }
        else if (w == 2) { in = Wv; out = WvT; }
        else             { in = Wo; out = WoT; }
    } else if (tb < 4608) {
        local = tb - 2304; in = Wm1; out = Wm1T; K = CDIM; N = C4; nx = 96;
    } else {
        local = tb - 4608; in = Wm2; out = Wm2T; K = C4; N = CDIM; nx = 24;
    }
    int bx = local % nx, by = local / nx;
    int k0 = by * 32, n0 = bx * 32;
    int tx = threadIdx.x & 31, ty = threadIdx.x >> 5;
#pragma unroll
    for (int i = 0; i < 4; i++)
        t[ty + i * 8][tx] = in[(size_t)(k0 + ty + i * 8) * N + n0 + tx];
    __syncthreads();
#pragma unroll
    for (int i = 0; i < 4; i++)
        out[(size_t)(n0 + ty + i * 8) * K + k0 + tx] = __float2half(t[tx][ty + i * 8]);
}

// ================= two-stage exact top-k =================
__global__ __launch_bounds__(512)
void topk_stage1(const float* __restrict__ scores, unsigned long long* __restrict__ part)
{
    __shared__ unsigned long long keys[512];
    int b = blockIdx.y, ch = blockIdx.x, tid = threadIdx.x;
    int t = ch * 512 + tid;
    unsigned int x = __float_as_uint(scores[(size_t)b * NS + t]);
    unsigned int u = (x & 0x80000000u) ? ~x : (x | 0x80000000u);
    keys[tid] = (((unsigned long long)(~u)) << 32) | (unsigned int)t;
    __syncthreads();
    for (int k = 2; k <= 512; k <<= 1) {
        for (int j = k >> 1; j > 0; j >>= 1) {
            int ixj = tid ^ j;
            if (ixj > tid) {
                bool up = ((tid & k) == 0);
                unsigned long long a = keys[tid], c = keys[ixj];
                if ((a > c) == up) { keys[tid] = c; keys[ixj] = a; }
            }
            __syncthreads();
        }
    }
    if (tid < TOPK)
        part[((size_t)b * 8 + ch) * TOPK + tid] = keys[tid];
}

__global__ __launch_bounds__(1024)
void topk_stage2(const unsigned long long* __restrict__ part,
                 const float* __restrict__ sampled,
                 float* __restrict__ topk_out,
                 float* __restrict__ sel_out, __half* __restrict__ sel_h)
{
    __shared__ unsigned long long keys[1024];
    int b = blockIdx.x, tid = threadIdx.x;
    keys[tid] = part[(size_t)b * 1024 + tid];
    __syncthreads();
    for (int k = 2; k <= 1024; k <<= 1) {
        for (int j = k >> 1; j > 0; j >>= 1) {
            int ixj = tid ^ j;
            if (ixj > tid) {
                bool up = ((tid & k) == 0);
                unsigned long long a = keys[tid], c = keys[ixj];
                if ((a > c) == up) { keys[tid] = c; keys[ixj] = a; }
            }
            __syncthreads();
        }
    }
    if (tid < TOPK)
        topk_out[b * TOPK + tid] = (float)(unsigned int)(keys[tid] & 0xFFFFFFFFull);
    for (int e = tid; e < TOPK * (CDIM / 4); e += 1024) {
        int kk = e / (CDIM / 4), c = e % (CDIM / 4);
        int idx = (int)(unsigned int)(keys[kk] & 0xFFFFFFFFull);
        float4 v = ((const float4*)(sampled + ((size_t)b * NS + idx) * CDIM))[c];
        size_t rowoff = ((size_t)b * TOPK + kk) * CDIM;
        ((float4*)(sel_out + rowoff))[c] = v;
        __half2* dh = (__half2*)(sel_h + rowoff) + c * 2;
        dh[0] = __floats2half2_rn(v.x, v.y);
        dh[1] = __floats2half2_rn(v.z, v.w);
    }
}

// ================= layernorm: warp per row =================
template <int OUTH>
__global__ __launch_bounds__(256)
void ln_kernel(const float* __restrict__ Xa, const float* __restrict__ Xb,
               const float* __restrict__ gam, const float* __restrict__ bet,
               float* __restrict__ outp, __half* __restrict__ outh)
{
    int warp = threadIdx.x >> 5, lane = threadIdx.x & 31;
    int row = blockIdx.x * 8 + warp;
    const float4* xa = (const float4*)(Xa + (size_t)row * CDIM);
    const float4* xb = (const float4*)(Xb + (size_t)row * CDIM);
    float x[24];
    float s = 0.f, ss = 0.f;
#pragma unroll
    for (int i = 0; i < 6; i++) {
        float4 a = xa[lane + i * 32];
        float4 b = xb[lane + i * 32];
        float v0 = a.x + b.x, v1 = a.y + b.y, v2 = a.z + b.z, v3 = a.w + b.w;
        x[i * 4] = v0; x[i * 4 + 1] = v1; x[i * 4 + 2] = v2; x[i * 4 + 3] = v3;
        s += v0 + v1 + v2 + v3;
        ss += v0 * v0 + v1 * v1 + v2 * v2 + v3 * v3;
    }
#pragma unroll
    for (int o = 16; o; o >>= 1) {
        s  += __shfl_xor_sync(0xffffffffu, s,  o);
        ss += __shfl_xor_sync(0xffffffffu, ss, o);
    }
    float mu = s * (1.0f / CDIM);
    float rstd = rsqrtf(ss * (1.0f / CDIM) - mu * mu + 1e-5f);
    const float4* gv = (const float4*)gam;
    const float4* bv = (const float4*)bet;
#pragma unroll
    for (int i = 0; i < 6; i++) {
        float4 gg = gv[lane + i * 32];
        float4 bb = bv[lane + i * 32];
        float y0 = (x[i * 4]     - mu) * rstd * gg.x + bb.x;
        float y1 = (x[i * 4 + 1] - mu) * rstd * gg.y + bb.y;
        float y2 = (x[i * 4 + 2] - mu) * rstd * gg.z + bb.z;
        float y3 = (x[i * 4 + 3] - mu) * rstd * gg.w + bb.w;
        ((float4*)(outp + (size_t)row * CDIM))[lane + i * 32] = make_float4(y0, y1, y2, y3);
        if (OUTH) {
            __half2* oh = (__half2*)(outh + (size_t)row * CDIM) + (lane + i * 32) * 2;
            oh[0] = __floats2half2_rn(y0, y1);
            oh[1] = __floats2half2_rn(y2, y3);
        }
    }
}

// ================= launch =================
extern "C" void kernel_launch(void* const* d_in, const int* in_sizes, int n_in,
                              void* d_out, int out_size)
{
    const float* base    = (const float*)d_in[0];
    const float* sampled = (const float*)d_in[1];
    const float* Wq = (const float*)d_in[2];  const float* bq = (const float*)d_in[3];
    const float* Wk = (const float*)d_in[4];  const float* bk = (const float*)d_in[5];
    const float* Wv = (const float*)d_in[6];  const float* bv = (const float*)d_in[7];
    const float* Wo = (const float*)d_in[8];  const float* bo = (const float*)d_in[9];
    const float* g1 = (const float*)d_in[10]; const float* b1 = (const float*)d_in[11];
    const float* g2 = (const float*)d_in[12]; const float* b2 = (const float*)d_in[13];
    const float* Wm1 = (const float*)d_in[14]; const float* bm1 = (const float*)d_in[15];
    const float* Wm2 = (const float*)d_in[16]; const float* bm2 = (const float*)d_in[17];

    float* out = (float*)d_out;
    float* out_x      = out;
    float* out_scores = out + (size_t)BATCH * NB * CDIM;
    float* out_attn   = out_scores + (size_t)BATCH * NS;
    float* out_topk   = out_attn + (size_t)BATCH * HEADS * NB * TOPK;
    float* out_sel    = out_topk + (size_t)BATCH * TOPK;

    float *p_tmp, *p_ctx, *p_x1;
    unsigned long long* p_part;
    __half *p_qh, *p_kh, *p_vh, *p_act, *p_selh, *p_h;
    __half *p_WqT, *p_WkT, *p_WvT, *p_WoT, *p_Wm1T, *p_Wm2T;
    __half *p_shi, *p_slo, *p_bhi, *p_blo;
    cudaGetSymbolAddress((void**)&p_tmp,  g_tmp);
    cudaGetSymbolAddress((void**)&p_ctx,  g_ctx);
    cudaGetSymbolAddress((void**)&p_x1,   g_x1);
    cudaGetSymbolAddress((void**)&p_part, g_part);
    cudaGetSymbolAddress((void**)&p_qh,   g_q_h);
    cudaGetSymbolAddress((void**)&p_kh,   g_k_h);
    cudaGetSymbolAddress((void**)&p_vh,   g_v_h);
    cudaGetSymbolAddress((void**)&p_act,  g_act_h);
    cudaGetSymbolAddress((void**)&p_selh, g_sel_h);
    cudaGetSymbolAddress((void**)&p_h,    g_h_h);
    cudaGetSymbolAddress((void**)&p_WqT,  g_WqT);
    cudaGetSymbolAddress((void**)&p_WkT,  g_WkT);
    cudaGetSymbolAddress((void**)&p_WvT,  g_WvT);
    cudaGetSymbolAddress((void**)&p_WoT,  g_WoT);
    cudaGetSymbolAddress((void**)&p_Wm1T, g_Wm1T);
    cudaGetSymbolAddress((void**)&p_Wm2T, g_Wm2T);
    cudaGetSymbolAddress((void**)&p_shi,  g_s_hi);
    cudaGetSymbolAddress((void**)&p_slo,  g_s_lo);
    cudaGetSymbolAddress((void**)&p_bhi,  g_b_hi);
    cudaGetSymbolAddress((void**)&p_blo,  g_b_lo);

    cudaFuncSetAttribute(gemm_mma<0,0>, cudaFuncAttributeMaxDynamicSharedMemorySize, G_SMEM);
    cudaFuncSetAttribute(gemm_mma<1,1>, cudaFuncAttributeMaxDynamicSharedMemorySize, G_SMEM);
    cudaFuncSetAttribute(gemm_qkv,      cudaFuncAttributeMaxDynamicSharedMemorySize, G_SMEM);
    cudaFuncSetAttribute(saliency_mma,  cudaFuncAttributeMaxDynamicSharedMemorySize, S2_SMEM);
    cudaFuncSetAttribute(attn_kernel,   cudaFuncAttributeMaxDynamicSharedMemorySize, AT_SMEM);

    const int M = BATCH * NB;

    transpose_all<<<6912, 256>>>(Wq, Wk, Wv, Wo, Wm1, Wm2,
                                 p_WqT, p_WkT, p_WvT, p_WoT, p_Wm1T, p_Wm2T);
    cvt_split_all<<<(N8S + N8B + 255) / 256, 256>>>(sampled, base, p_shi, p_slo, p_bhi, p_blo);

    saliency_mma<<<dim3(NS/128, BATCH), 512, S2_SMEM>>>(p_shi, p_slo, p_bhi, p_blo, out_scores);
    topk_stage1<<<dim3(8, BATCH), 512>>>(out_scores, p_part);
    topk_stage2<<<BATCH, 1024>>>(p_part, sampled, out_topk, out_sel, p_selh);

    gemm_qkv<<<dim3(CDIM/128, 160), 256, G_SMEM>>>(p_bhi, p_selh, p_WqT, p_WkT, p_WvT,
                                                   bq, bk, bv, p_qh, p_kh, p_vh);

    attn_kernel<<<dim3(NB/128, HEADS, BATCH), 256, AT_SMEM>>>(p_qh, p_kh, p_vh, out_attn, p_act);

    gemm_mma<0,0><<<dim3(CDIM/128, M/128), 256, G_SMEM>>>(p_act, p_WoT, bo, p_tmp, nullptr, M, CDIM, CDIM);

    ln_kernel<1><<<M/8, 256>>>(base, p_tmp, g1, b1, p_x1, p_act);
    gemm_mma<1,1><<<dim3(C4/128, M/128), 256, G_SMEM>>>(p_act, p_Wm1T, bm1, nullptr, p_h, M, C4, CDIM);
    gemm_mma<0,0><<<dim3(CDIM/128, M/128), 256, G_SMEM>>>(p_h, p_Wm2T, bm2, p_ctx, nullptr, M, CDIM, C4);
    ln_kernel<0><<<M/8, 256>>>(p_x1, p_ctx, g2, b2, out_x, nullptr);
}